// round 4
// baseline (speedup 1.0000x reference)
#include <cuda_runtime.h>

#define NV   2562
#define DEG  8
#define FIN  8
#define FOUT 16
#define KCH  5
#define SP   512                 // spatial = X*Y*Z
#define SP4  (SP/4)              // 128 float4 per (v,f) row-chunk
#define DD   (FIN*SP)            // 4096 floats per vertex row
#define DD4  (DD/4)              // 1024 float4

// Scratch: 3 rolling Chebyshev levels (x1, x2, x3), 42 MB each.
__device__ float4 g_buf[3][(size_t)NV * DD4];

// One block per vertex v; 128 threads cover the 512 spatial floats as float4.
// Two f-iterations interleaved -> 16 independent gather loads in flight.
__global__ __launch_bounds__(SP4) void spmv_step_kernel(
    const float4* __restrict__ cur,  int cvs4, int cfs4,   // strides in float4 units
    const float4* __restrict__ prev, int pvs4, int pfs4,
    float4* __restrict__ next,
    const int* __restrict__ cols, const float* __restrict__ vals,
    int has_prev)
{
    __shared__ int   scol[DEG];
    __shared__ float sval[DEG];
    const int v = blockIdx.x;
    const int t = threadIdx.x;
    if (t < DEG) {
        scol[t] = cols[v * DEG + t];
        sval[t] = vals[v * DEG + t];
    }
    __syncthreads();

    #pragma unroll
    for (int f = 0; f < FIN; f += 2) {
        float4 a0 = make_float4(0.f, 0.f, 0.f, 0.f);
        float4 a1 = make_float4(0.f, 0.f, 0.f, 0.f);
        #pragma unroll
        for (int n = 0; n < DEG; ++n) {
            const size_t base = (size_t)scol[n] * cvs4 + (size_t)f * cfs4 + t;
            const float4 x0 = cur[base];
            const float4 x1 = cur[base + cfs4];
            const float  w  = sval[n];
            a0.x += w * x0.x; a0.y += w * x0.y; a0.z += w * x0.z; a0.w += w * x0.w;
            a1.x += w * x1.x; a1.y += w * x1.y; a1.z += w * x1.z; a1.w += w * x1.w;
        }
        if (has_prev) {
            const float4 p0 = prev[(size_t)v * pvs4 + (size_t)f * pfs4 + t];
            const float4 p1 = prev[(size_t)v * pvs4 + (size_t)(f + 1) * pfs4 + t];
            a0.x = 2.f * a0.x - p0.x; a0.y = 2.f * a0.y - p0.y;
            a0.z = 2.f * a0.z - p0.z; a0.w = 2.f * a0.w - p0.w;
            a1.x = 2.f * a1.x - p1.x; a1.y = 2.f * a1.y - p1.y;
            a1.z = 2.f * a1.z - p1.z; a1.w = 2.f * a1.w - p1.w;
        }
        next[(size_t)v * DD4 + f * SP4 + t]       = a0;
        next[(size_t)v * DD4 + (f + 1) * SP4 + t] = a1;
    }
}

// Final: grid (NV, 2). Each block computes x4 row into smem (phase 1), then
// its 256 threads split into 2 o-subgroups x 128 spatial threads; each thread
// accumulates only 4 outputs (c[4] float4 = 16 regs) -> ~3 blocks/SM.
__global__ __launch_bounds__(2 * SP4, 3) void final_kernel(
    const float4* __restrict__ x0,
    const float4* __restrict__ x1,
    const float4* __restrict__ x2,
    const float4* __restrict__ x3,
    const int* __restrict__ cols, const float* __restrict__ vals,
    const float* __restrict__ weight, const float* __restrict__ bias,
    float4* __restrict__ out)
{
    __shared__ int    scol[DEG];
    __shared__ float  sval[DEG];
    __shared__ float  sw[KCH * FIN * FOUT];   // 640 floats, [k][f][o]
    __shared__ float  sb[FOUT];
    __shared__ float4 sx4[FIN * SP4];         // 16 KB: x4 row for this vertex

    const int v   = blockIdx.x;
    const int tid = threadIdx.x;

    if (tid < DEG) {
        scol[tid] = cols[v * DEG + tid];
        sval[tid] = vals[v * DEG + tid];
    }
    for (int i = tid; i < KCH * FIN * FOUT; i += blockDim.x) sw[i] = weight[i];
    if (tid < FOUT) sb[tid] = bias[tid];
    __syncthreads();

    // Phase 1: all 256 threads compute x4[v, f, t] = 2*spmv(x3) - x2 into smem.
    #pragma unroll
    for (int j = 0; j < (FIN * SP4) / (2 * SP4); ++j) {   // 4 iterations
        const int idx = tid + j * (2 * SP4);
        const int f   = idx >> 7;          // /128
        const int t   = idx & (SP4 - 1);
        float4 acc = make_float4(0.f, 0.f, 0.f, 0.f);
        #pragma unroll
        for (int n = 0; n < DEG; ++n) {
            const float4 x = x3[(size_t)scol[n] * DD4 + f * SP4 + t];
            const float  w = sval[n];
            acc.x += w * x.x; acc.y += w * x.y;
            acc.z += w * x.z; acc.w += w * x.w;
        }
        const float4 p2 = x2[(size_t)v * DD4 + f * SP4 + t];
        acc.x = 2.f * acc.x - p2.x; acc.y = 2.f * acc.y - p2.y;
        acc.z = 2.f * acc.z - p2.z; acc.w = 2.f * acc.w - p2.w;
        sx4[idx] = acc;
    }
    __syncthreads();

    // Phase 2: o-split. This block covers outputs [blockIdx.y*8, +8);
    // threads [0,128) -> first 4, [128,256) -> next 4.
    const int half   = tid >> 7;                       // 0 or 1
    const int o_base = blockIdx.y * (FOUT / 2) + half * (FOUT / 4);
    const int t      = tid & (SP4 - 1);

    float4 c[FOUT / 4];
    #pragma unroll
    for (int oo = 0; oo < FOUT / 4; ++oo) {
        const float b = sb[o_base + oo];
        c[oo] = make_float4(b, b, b, b);
    }

    #pragma unroll
    for (int f = 0; f < FIN; ++f) {
        const float4 x0f = x0[(size_t)f * (NV * SP4) + (size_t)v * SP4 + t];
        const float4 x1f = x1[(size_t)v * DD4 + f * SP4 + t];
        const float4 x2f = x2[(size_t)v * DD4 + f * SP4 + t];
        const float4 x3f = x3[(size_t)v * DD4 + f * SP4 + t];
        const float4 x4f = sx4[f * SP4 + t];

        #pragma unroll
        for (int oo = 0; oo < FOUT / 4; ++oo) {
            const int o = o_base + oo;
            const float w0 = sw[0 * FIN * FOUT + f * FOUT + o];
            const float w1 = sw[1 * FIN * FOUT + f * FOUT + o];
            const float w2 = sw[2 * FIN * FOUT + f * FOUT + o];
            const float w3 = sw[3 * FIN * FOUT + f * FOUT + o];
            const float w4 = sw[4 * FIN * FOUT + f * FOUT + o];
            c[oo].x += x0f.x*w0 + x1f.x*w1 + x2f.x*w2 + x3f.x*w3 + x4f.x*w4;
            c[oo].y += x0f.y*w0 + x1f.y*w1 + x2f.y*w2 + x3f.y*w3 + x4f.y*w4;
            c[oo].z += x0f.z*w0 + x1f.z*w1 + x2f.z*w2 + x3f.z*w3 + x4f.z*w4;
            c[oo].w += x0f.w*w0 + x1f.w*w1 + x2f.w*w2 + x3f.w*w3 + x4f.w*w4;
        }
    }

    #pragma unroll
    for (int oo = 0; oo < FOUT / 4; ++oo)
        out[(size_t)(o_base + oo) * (NV * SP4) + (size_t)v * SP4 + t] = c[oo];
}

extern "C" void kernel_launch(void* const* d_in, const int* in_sizes, int n_in,
                              void* d_out, int out_size) {
    const float* inputs = (const float*)d_in[0];
    // d_in[1] = lap_rows (unused: rows are repeat(arange(V), DEG) by construction)
    const int*   cols   = (const int*)d_in[2];
    const float* vals   = (const float*)d_in[3];
    const float* weight = (const float*)d_in[4];
    const float* bias   = (const float*)d_in[5];
    float4*      out    = (float4*)d_out;

    void* sym = nullptr;
    cudaGetSymbolAddress(&sym, g_buf);
    float4* g0 = (float4*)sym;
    float4* g1 = g0 + (size_t)NV * DD4;
    float4* g2 = g1 + (size_t)NV * DD4;

    const float4* in4 = (const float4*)inputs;
    const int IVS4 = SP4;            // input vertex stride (float4)
    const int IFS4 = NV * SP4;       // input feature stride (float4)

    // x1 = L @ x0 (x0 read directly from inputs layout)
    spmv_step_kernel<<<NV, SP4>>>(in4, IVS4, IFS4, nullptr, 0, 0,
                                  g0, cols, vals, 0);
    // x2 = 2 L x1 - x0
    spmv_step_kernel<<<NV, SP4>>>(g0, DD4, SP4, in4, IVS4, IFS4,
                                  g1, cols, vals, 1);
    // x3 = 2 L x2 - x1
    spmv_step_kernel<<<NV, SP4>>>(g1, DD4, SP4, g0, DD4, SP4,
                                  g2, cols, vals, 1);
    // x4 (smem) + einsum over (k,f) + bias -> out; FOUT split over grid.y + halves
    dim3 fgrid(NV, 2);
    final_kernel<<<fgrid, 2 * SP4>>>(in4, g0, g1, g2, cols, vals, weight, bias, out);
}

// round 5
// speedup vs baseline: 1.0808x; 1.0808x over previous
#include <cuda_runtime.h>

#define NV   2562
#define DEG  8
#define FIN  8
#define FOUT 16
#define KCH  5
#define SP   512                 // spatial = X*Y*Z
#define SP4  (SP/4)              // 128 float4 per (v,f) row-chunk
#define DD   (FIN*SP)            // 4096 floats per vertex row
#define DD4  (DD/4)              // 1024 float4

// Scratch: 3 rolling Chebyshev levels (x1, x2, x3), 42 MB each.
__device__ float4 g_buf[3][(size_t)NV * DD4];

// One block per vertex v; 128 threads cover the 512 spatial floats as float4.
// Two f-iterations interleaved -> 16 independent gather loads in flight.
__global__ __launch_bounds__(SP4) void spmv_step_kernel(
    const float4* __restrict__ cur,  int cvs4, int cfs4,   // strides in float4 units
    const float4* __restrict__ prev, int pvs4, int pfs4,
    float4* __restrict__ next,
    const int* __restrict__ cols, const float* __restrict__ vals,
    int has_prev)
{
    __shared__ int   scol[DEG];
    __shared__ float sval[DEG];
    const int v = blockIdx.x;
    const int t = threadIdx.x;
    if (t < DEG) {
        scol[t] = cols[v * DEG + t];
        sval[t] = vals[v * DEG + t];
    }
    __syncthreads();

    #pragma unroll
    for (int f = 0; f < FIN; f += 2) {
        float4 a0 = make_float4(0.f, 0.f, 0.f, 0.f);
        float4 a1 = make_float4(0.f, 0.f, 0.f, 0.f);
        #pragma unroll
        for (int n = 0; n < DEG; ++n) {
            const size_t base = (size_t)scol[n] * cvs4 + (size_t)f * cfs4 + t;
            const float4 x0 = cur[base];
            const float4 x1 = cur[base + cfs4];
            const float  w  = sval[n];
            a0.x += w * x0.x; a0.y += w * x0.y; a0.z += w * x0.z; a0.w += w * x0.w;
            a1.x += w * x1.x; a1.y += w * x1.y; a1.z += w * x1.z; a1.w += w * x1.w;
        }
        if (has_prev) {
            const float4 p0 = prev[(size_t)v * pvs4 + (size_t)f * pfs4 + t];
            const float4 p1 = prev[(size_t)v * pvs4 + (size_t)(f + 1) * pfs4 + t];
            a0.x = 2.f * a0.x - p0.x; a0.y = 2.f * a0.y - p0.y;
            a0.z = 2.f * a0.z - p0.z; a0.w = 2.f * a0.w - p0.w;
            a1.x = 2.f * a1.x - p1.x; a1.y = 2.f * a1.y - p1.y;
            a1.z = 2.f * a1.z - p1.z; a1.w = 2.f * a1.w - p1.w;
        }
        next[(size_t)v * DD4 + f * SP4 + t]       = a0;
        next[(size_t)v * DD4 + (f + 1) * SP4 + t] = a1;
    }
}

// Final: one block per vertex, 512 threads. Phase 1: cooperative x4 gather
// into smem. Phase 2: 4 o-groups x 128 spatial threads; each thread carries
// c[4] float4. The 4 o-groups re-read identical row addresses concurrently
// -> L1 broadcast, no extra L2/DRAM traffic.
__global__ __launch_bounds__(4 * SP4, 2) void final_kernel(
    const float4* __restrict__ x0,
    const float4* __restrict__ x1,
    const float4* __restrict__ x2,
    const float4* __restrict__ x3,
    const int* __restrict__ cols, const float* __restrict__ vals,
    const float* __restrict__ weight, const float* __restrict__ bias,
    float4* __restrict__ out)
{
    __shared__ int    scol[DEG];
    __shared__ float  sval[DEG];
    __shared__ float  sw[KCH * FIN * FOUT];   // 640 floats, [k][f][o]
    __shared__ float  sb[FOUT];
    __shared__ float4 sx4[FIN * SP4];         // 16 KB: x4 row for this vertex

    const int v   = blockIdx.x;
    const int tid = threadIdx.x;

    if (tid < DEG) {
        scol[tid] = cols[v * DEG + tid];
        sval[tid] = vals[v * DEG + tid];
    }
    for (int i = tid; i < KCH * FIN * FOUT; i += blockDim.x) sw[i] = weight[i];
    if (tid < FOUT) sb[tid] = bias[tid];
    __syncthreads();

    // Phase 1: 512 threads compute x4[v, f, t] = 2*spmv(x3) - x2 into smem.
    #pragma unroll
    for (int j = 0; j < (FIN * SP4) / (4 * SP4); ++j) {   // 2 iterations
        const int idx = tid + j * (4 * SP4);
        const int f   = idx >> 7;          // /128
        const int t   = idx & (SP4 - 1);
        float4 acc = make_float4(0.f, 0.f, 0.f, 0.f);
        #pragma unroll
        for (int n = 0; n < DEG; ++n) {
            const float4 x = x3[(size_t)scol[n] * DD4 + f * SP4 + t];
            const float  w = sval[n];
            acc.x += w * x.x; acc.y += w * x.y;
            acc.z += w * x.z; acc.w += w * x.w;
        }
        const float4 p2 = x2[(size_t)v * DD4 + f * SP4 + t];
        acc.x = 2.f * acc.x - p2.x; acc.y = 2.f * acc.y - p2.y;
        acc.z = 2.f * acc.z - p2.z; acc.w = 2.f * acc.w - p2.w;
        sx4[idx] = acc;
    }
    __syncthreads();

    // Phase 2: 4 o-groups x 128 spatial threads.
    const int grp    = tid >> 7;                 // 0..3
    const int o_base = grp * (FOUT / 4);
    const int t      = tid & (SP4 - 1);

    float4 c[FOUT / 4];
    #pragma unroll
    for (int oo = 0; oo < FOUT / 4; ++oo) {
        const float b = sb[o_base + oo];
        c[oo] = make_float4(b, b, b, b);
    }

    #pragma unroll
    for (int f = 0; f < FIN; ++f) {
        const float4 x0f = x0[(size_t)f * (NV * SP4) + (size_t)v * SP4 + t];
        const float4 x1f = x1[(size_t)v * DD4 + f * SP4 + t];
        const float4 x2f = x2[(size_t)v * DD4 + f * SP4 + t];
        const float4 x3f = x3[(size_t)v * DD4 + f * SP4 + t];
        const float4 x4f = sx4[f * SP4 + t];

        #pragma unroll
        for (int oo = 0; oo < FOUT / 4; ++oo) {
            const int o = o_base + oo;
            const float w0 = sw[0 * FIN * FOUT + f * FOUT + o];
            const float w1 = sw[1 * FIN * FOUT + f * FOUT + o];
            const float w2 = sw[2 * FIN * FOUT + f * FOUT + o];
            const float w3 = sw[3 * FIN * FOUT + f * FOUT + o];
            const float w4 = sw[4 * FIN * FOUT + f * FOUT + o];
            c[oo].x += x0f.x*w0 + x1f.x*w1 + x2f.x*w2 + x3f.x*w3 + x4f.x*w4;
            c[oo].y += x0f.y*w0 + x1f.y*w1 + x2f.y*w2 + x3f.y*w3 + x4f.y*w4;
            c[oo].z += x0f.z*w0 + x1f.z*w1 + x2f.z*w2 + x3f.z*w3 + x4f.z*w4;
            c[oo].w += x0f.w*w0 + x1f.w*w1 + x2f.w*w2 + x3f.w*w3 + x4f.w*w4;
        }
    }

    #pragma unroll
    for (int oo = 0; oo < FOUT / 4; ++oo)
        out[(size_t)(o_base + oo) * (NV * SP4) + (size_t)v * SP4 + t] = c[oo];
}

extern "C" void kernel_launch(void* const* d_in, const int* in_sizes, int n_in,
                              void* d_out, int out_size) {
    const float* inputs = (const float*)d_in[0];
    // d_in[1] = lap_rows (unused: rows are repeat(arange(V), DEG) by construction)
    const int*   cols   = (const int*)d_in[2];
    const float* vals   = (const float*)d_in[3];
    const float* weight = (const float*)d_in[4];
    const float* bias   = (const float*)d_in[5];
    float4*      out    = (float4*)d_out;

    void* sym = nullptr;
    cudaGetSymbolAddress(&sym, g_buf);
    float4* g0 = (float4*)sym;
    float4* g1 = g0 + (size_t)NV * DD4;
    float4* g2 = g1 + (size_t)NV * DD4;

    const float4* in4 = (const float4*)inputs;
    const int IVS4 = SP4;            // input vertex stride (float4)
    const int IFS4 = NV * SP4;       // input feature stride (float4)

    // x1 = L @ x0 (x0 read directly from inputs layout)
    spmv_step_kernel<<<NV, SP4>>>(in4, IVS4, IFS4, nullptr, 0, 0,
                                  g0, cols, vals, 0);
    // x2 = 2 L x1 - x0
    spmv_step_kernel<<<NV, SP4>>>(g0, DD4, SP4, in4, IVS4, IFS4,
                                  g1, cols, vals, 1);
    // x3 = 2 L x2 - x1
    spmv_step_kernel<<<NV, SP4>>>(g1, DD4, SP4, g0, DD4, SP4,
                                  g2, cols, vals, 1);
    // x4 (smem) + einsum over (k,f) + bias -> out; o-split inside the block
    final_kernel<<<NV, 4 * SP4>>>(in4, g0, g1, g2, cols, vals, weight, bias, out);
}

// round 6
// speedup vs baseline: 1.1423x; 1.0570x over previous
#include <cuda_runtime.h>

#define NV   2562
#define DEG  8
#define FIN  8
#define FOUT 16
#define KCH  5
#define SP   512                 // spatial = X*Y*Z
#define SP4  (SP/4)              // 128 float4 per (v,f) row-chunk
#define DD   (FIN*SP)            // 4096 floats per vertex row
#define DD4  (DD/4)              // 1024 float4

// Scratch: 3 rolling Chebyshev levels (x1, x2, x3), 42 MB each.
__device__ float4 g_buf[3][(size_t)NV * DD4];

// Weights/bias in constant memory: LDCU (uniform-register path) instead of
// GPR-cached smem loads -> frees ~40 GPRs in the final kernel.
__constant__ float c_w[KCH * FIN * FOUT];
__constant__ float c_b[FOUT];

// One block per vertex v; 128 threads cover the 512 spatial floats as float4.
// Two f-iterations interleaved -> 16 independent gather loads in flight.
__global__ __launch_bounds__(SP4) void spmv_step_kernel(
    const float4* __restrict__ cur,  int cvs4, int cfs4,   // strides in float4 units
    const float4* __restrict__ prev, int pvs4, int pfs4,
    float4* __restrict__ next,
    const int* __restrict__ cols, const float* __restrict__ vals,
    int has_prev)
{
    __shared__ int   scol[DEG];
    __shared__ float sval[DEG];
    const int v = blockIdx.x;
    const int t = threadIdx.x;
    if (t < DEG) {
        scol[t] = cols[v * DEG + t];
        sval[t] = vals[v * DEG + t];
    }
    __syncthreads();

    #pragma unroll
    for (int f = 0; f < FIN; f += 2) {
        float4 a0 = make_float4(0.f, 0.f, 0.f, 0.f);
        float4 a1 = make_float4(0.f, 0.f, 0.f, 0.f);
        #pragma unroll
        for (int n = 0; n < DEG; ++n) {
            const size_t base = (size_t)scol[n] * cvs4 + (size_t)f * cfs4 + t;
            const float4 x0 = cur[base];
            const float4 x1 = cur[base + cfs4];
            const float  w  = sval[n];
            a0.x += w * x0.x; a0.y += w * x0.y; a0.z += w * x0.z; a0.w += w * x0.w;
            a1.x += w * x1.x; a1.y += w * x1.y; a1.z += w * x1.z; a1.w += w * x1.w;
        }
        if (has_prev) {
            const float4 p0 = prev[(size_t)v * pvs4 + (size_t)f * pfs4 + t];
            const float4 p1 = prev[(size_t)v * pvs4 + (size_t)(f + 1) * pfs4 + t];
            a0.x = 2.f * a0.x - p0.x; a0.y = 2.f * a0.y - p0.y;
            a0.z = 2.f * a0.z - p0.z; a0.w = 2.f * a0.w - p0.w;
            a1.x = 2.f * a1.x - p1.x; a1.y = 2.f * a1.y - p1.y;
            a1.z = 2.f * a1.z - p1.z; a1.w = 2.f * a1.w - p1.w;
        }
        next[(size_t)v * DD4 + f * SP4 + t]       = a0;
        next[(size_t)v * DD4 + (f + 1) * SP4 + t] = a1;
    }
}

// Final (R3 structure + constant weights + reg cap): one block per vertex,
// 256 threads. Phase 1: cooperative x4 gather into smem. Phase 2: two
// o-groups x 128 spatial threads, each thread accumulates 8 outputs.
__global__ __launch_bounds__(2 * SP4, 3) void final_kernel(
    const float4* __restrict__ x0,
    const float4* __restrict__ x1,
    const float4* __restrict__ x2,
    const float4* __restrict__ x3,
    const int* __restrict__ cols, const float* __restrict__ vals,
    float4* __restrict__ out)
{
    __shared__ int    scol[DEG];
    __shared__ float  sval[DEG];
    __shared__ float4 sx4[FIN * SP4];         // 16 KB: x4 row for this vertex

    const int v   = blockIdx.x;
    const int tid = threadIdx.x;

    if (tid < DEG) {
        scol[tid] = cols[v * DEG + tid];
        sval[tid] = vals[v * DEG + tid];
    }
    __syncthreads();

    // Phase 1: 256 threads compute x4[v, f, t] = 2*spmv(x3) - x2 into smem.
    #pragma unroll
    for (int j = 0; j < (FIN * SP4) / (2 * SP4); ++j) {   // 4 iterations
        const int idx = tid + j * (2 * SP4);
        const int f   = idx >> 7;          // /128
        const int t   = idx & (SP4 - 1);
        float4 acc = make_float4(0.f, 0.f, 0.f, 0.f);
        #pragma unroll
        for (int n = 0; n < DEG; ++n) {
            const float4 x = x3[(size_t)scol[n] * DD4 + f * SP4 + t];
            const float  w = sval[n];
            acc.x += w * x.x; acc.y += w * x.y;
            acc.z += w * x.z; acc.w += w * x.w;
        }
        const float4 p2 = x2[(size_t)v * DD4 + f * SP4 + t];
        acc.x = 2.f * acc.x - p2.x; acc.y = 2.f * acc.y - p2.y;
        acc.z = 2.f * acc.z - p2.z; acc.w = 2.f * acc.w - p2.w;
        sx4[idx] = acc;
    }
    __syncthreads();

    // Phase 2: o-group split. Threads [0,128) -> o=0..7, [128,256) -> o=8..15.
    const int half   = tid >> 7;           // 0 or 1
    const int o_base = half * (FOUT / 2);
    const int t      = tid & (SP4 - 1);

    float4 c[FOUT / 2];
    #pragma unroll
    for (int oo = 0; oo < FOUT / 2; ++oo) {
        const float b = c_b[o_base + oo];
        c[oo] = make_float4(b, b, b, b);
    }

    #pragma unroll
    for (int f = 0; f < FIN; ++f) {
        const float4 x0f = x0[(size_t)f * (NV * SP4) + (size_t)v * SP4 + t];
        const float4 x1f = x1[(size_t)v * DD4 + f * SP4 + t];
        const float4 x2f = x2[(size_t)v * DD4 + f * SP4 + t];
        const float4 x3f = x3[(size_t)v * DD4 + f * SP4 + t];
        const float4 x4f = sx4[f * SP4 + t];

        #pragma unroll
        for (int oo = 0; oo < FOUT / 2; ++oo) {
            const int o = o_base + oo;
            const float w0 = c_w[0 * FIN * FOUT + f * FOUT + o];
            const float w1 = c_w[1 * FIN * FOUT + f * FOUT + o];
            const float w2 = c_w[2 * FIN * FOUT + f * FOUT + o];
            const float w3 = c_w[3 * FIN * FOUT + f * FOUT + o];
            const float w4 = c_w[4 * FIN * FOUT + f * FOUT + o];
            c[oo].x += x0f.x*w0 + x1f.x*w1 + x2f.x*w2 + x3f.x*w3 + x4f.x*w4;
            c[oo].y += x0f.y*w0 + x1f.y*w1 + x2f.y*w2 + x3f.y*w3 + x4f.y*w4;
            c[oo].z += x0f.z*w0 + x1f.z*w1 + x2f.z*w2 + x3f.z*w3 + x4f.z*w4;
            c[oo].w += x0f.w*w0 + x1f.w*w1 + x2f.w*w2 + x3f.w*w3 + x4f.w*w4;
        }
    }

    #pragma unroll
    for (int oo = 0; oo < FOUT / 2; ++oo)
        out[(size_t)(o_base + oo) * (NV * SP4) + (size_t)v * SP4 + t] = c[oo];
}

extern "C" void kernel_launch(void* const* d_in, const int* in_sizes, int n_in,
                              void* d_out, int out_size) {
    const float* inputs = (const float*)d_in[0];
    // d_in[1] = lap_rows (unused: rows are repeat(arange(V), DEG) by construction)
    const int*   cols   = (const int*)d_in[2];
    const float* vals   = (const float*)d_in[3];
    const float* weight = (const float*)d_in[4];
    const float* bias   = (const float*)d_in[5];
    float4*      out    = (float4*)d_out;

    void* sym = nullptr;
    cudaGetSymbolAddress(&sym, g_buf);
    float4* g0 = (float4*)sym;
    float4* g1 = g0 + (size_t)NV * DD4;
    float4* g2 = g1 + (size_t)NV * DD4;

    // Stage weights/bias into constant memory (capturable D2D memcpy nodes).
    cudaMemcpyToSymbolAsync(c_w, weight, KCH * FIN * FOUT * sizeof(float), 0,
                            cudaMemcpyDeviceToDevice, 0);
    cudaMemcpyToSymbolAsync(c_b, bias, FOUT * sizeof(float), 0,
                            cudaMemcpyDeviceToDevice, 0);

    const float4* in4 = (const float4*)inputs;
    const int IVS4 = SP4;            // input vertex stride (float4)
    const int IFS4 = NV * SP4;       // input feature stride (float4)

    // x1 = L @ x0 (x0 read directly from inputs layout)
    spmv_step_kernel<<<NV, SP4>>>(in4, IVS4, IFS4, nullptr, 0, 0,
                                  g0, cols, vals, 0);
    // x2 = 2 L x1 - x0
    spmv_step_kernel<<<NV, SP4>>>(g0, DD4, SP4, in4, IVS4, IFS4,
                                  g1, cols, vals, 1);
    // x3 = 2 L x2 - x1
    spmv_step_kernel<<<NV, SP4>>>(g1, DD4, SP4, g0, DD4, SP4,
                                  g2, cols, vals, 1);
    // x4 (smem) + einsum over (k,f) + bias -> out
    final_kernel<<<NV, 2 * SP4>>>(in4, g0, g1, g2, cols, vals, out);
}

// round 7
// speedup vs baseline: 1.1682x; 1.0227x over previous
#include <cuda_runtime.h>

#define NV   2562
#define DEG  8
#define FIN  8
#define FOUT 16
#define KCH  5
#define SP   512                 // spatial = X*Y*Z
#define SP4  (SP/4)              // 128 float4 per (v,f) row-chunk
#define DD   (FIN*SP)            // 4096 floats per vertex row
#define DD4  (DD/4)              // 1024 float4

// Scratch: 3 rolling Chebyshev levels (x1, x2, x3), 42 MB each.
__device__ float4 g_buf[3][(size_t)NV * DD4];

// One block per vertex v; 128 threads cover the 512 spatial floats as float4.
// Two f-iterations interleaved -> 16 independent gather loads in flight.
__global__ __launch_bounds__(SP4) void spmv_step_kernel(
    const float4* __restrict__ cur,  int cvs4, int cfs4,   // strides in float4 units
    const float4* __restrict__ prev, int pvs4, int pfs4,
    float4* __restrict__ next,
    const int* __restrict__ cols, const float* __restrict__ vals,
    int has_prev)
{
    __shared__ int   scol[DEG];
    __shared__ float sval[DEG];
    const int v = blockIdx.x;
    const int t = threadIdx.x;
    if (t < DEG) {
        scol[t] = cols[v * DEG + t];
        sval[t] = vals[v * DEG + t];
    }
    __syncthreads();

    #pragma unroll
    for (int f = 0; f < FIN; f += 2) {
        float4 a0 = make_float4(0.f, 0.f, 0.f, 0.f);
        float4 a1 = make_float4(0.f, 0.f, 0.f, 0.f);
        #pragma unroll
        for (int n = 0; n < DEG; ++n) {
            const size_t base = (size_t)scol[n] * cvs4 + (size_t)f * cfs4 + t;
            const float4 x0 = cur[base];
            const float4 x1 = cur[base + cfs4];
            const float  w  = sval[n];
            a0.x += w * x0.x; a0.y += w * x0.y; a0.z += w * x0.z; a0.w += w * x0.w;
            a1.x += w * x1.x; a1.y += w * x1.y; a1.z += w * x1.z; a1.w += w * x1.w;
        }
        if (has_prev) {
            const float4 p0 = prev[(size_t)v * pvs4 + (size_t)f * pfs4 + t];
            const float4 p1 = prev[(size_t)v * pvs4 + (size_t)(f + 1) * pfs4 + t];
            a0.x = 2.f * a0.x - p0.x; a0.y = 2.f * a0.y - p0.y;
            a0.z = 2.f * a0.z - p0.z; a0.w = 2.f * a0.w - p0.w;
            a1.x = 2.f * a1.x - p1.x; a1.y = 2.f * a1.y - p1.y;
            a1.z = 2.f * a1.z - p1.z; a1.w = 2.f * a1.w - p1.w;
        }
        next[(size_t)v * DD4 + f * SP4 + t]       = a0;
        next[(size_t)v * DD4 + (f + 1) * SP4 + t] = a1;
    }
}

// Final, smem-staged: one block per vertex, 256 threads, 83 KB dynamic smem.
// Phase 1: 12 batched global loads/thread/iter stage x0..x3 rows + computed
// x4 into smem (each byte read once). Phase 2: o-half split contraction with
// ZERO global traffic (LDS only).
__global__ __launch_bounds__(2 * SP4, 2) void final_kernel(
    const float4* __restrict__ x0,
    const float4* __restrict__ x1,
    const float4* __restrict__ x2,
    const float4* __restrict__ x3,
    const int* __restrict__ cols, const float* __restrict__ vals,
    const float* __restrict__ weight, const float* __restrict__ bias,
    float4* __restrict__ out)
{
    extern __shared__ float4 smem[];
    float4* slev = smem;                                  // [5][FIN*SP4] = 80 KB
    float*  sw   = (float*)(smem + KCH * FIN * SP4);      // 640 floats
    float*  sb   = sw + KCH * FIN * FOUT;                 // 16 floats
    int*    scol = (int*)(sb + FOUT);                     // 8
    float*  sval = (float*)(scol + DEG);                  // 8

    const int v   = blockIdx.x;
    const int tid = threadIdx.x;

    if (tid < DEG) {
        scol[tid] = cols[v * DEG + tid];
        sval[tid] = vals[v * DEG + tid];
    }
    for (int i = tid; i < KCH * FIN * FOUT; i += 2 * SP4) sw[i] = weight[i];
    if (tid < FOUT) sb[tid] = bias[tid];
    __syncthreads();

    // Phase 1: stage x0..x3 rows and compute x4 -> smem.
    #pragma unroll 1
    for (int j = 0; j < (FIN * SP4) / (2 * SP4); ++j) {   // 4 iterations
        const int idx = tid + j * (2 * SP4);
        const int f   = idx >> 7;          // /128
        const int t   = idx & (SP4 - 1);

        // 12 independent global loads, front-batched.
        const float4 x0v = x0[(size_t)f * (NV * SP4) + (size_t)v * SP4 + t];
        const float4 x1v = x1[(size_t)v * DD4 + f * SP4 + t];
        const float4 x2v = x2[(size_t)v * DD4 + f * SP4 + t];
        const float4 x3v = x3[(size_t)v * DD4 + f * SP4 + t];

        float4 acc = make_float4(0.f, 0.f, 0.f, 0.f);
        #pragma unroll
        for (int n = 0; n < DEG; ++n) {
            const float4 x = x3[(size_t)scol[n] * DD4 + f * SP4 + t];
            const float  w = sval[n];
            acc.x += w * x.x; acc.y += w * x.y;
            acc.z += w * x.z; acc.w += w * x.w;
        }
        acc.x = 2.f * acc.x - x2v.x; acc.y = 2.f * acc.y - x2v.y;
        acc.z = 2.f * acc.z - x2v.z; acc.w = 2.f * acc.w - x2v.w;

        slev[0 * FIN * SP4 + idx] = x0v;
        slev[1 * FIN * SP4 + idx] = x1v;
        slev[2 * FIN * SP4 + idx] = x2v;
        slev[3 * FIN * SP4 + idx] = x3v;
        slev[4 * FIN * SP4 + idx] = acc;
    }
    __syncthreads();

    // Phase 2: o-half split; all operands from smem.
    const int half   = tid >> 7;           // 0 or 1
    const int o_base = half * (FOUT / 2);
    const int t      = tid & (SP4 - 1);

    float4 c[FOUT / 2];
    #pragma unroll
    for (int oo = 0; oo < FOUT / 2; ++oo) {
        const float b = sb[o_base + oo];
        c[oo] = make_float4(b, b, b, b);
    }

    #pragma unroll 1
    for (int f = 0; f < FIN; ++f) {
        const float4 xk0 = slev[0 * FIN * SP4 + f * SP4 + t];
        const float4 xk1 = slev[1 * FIN * SP4 + f * SP4 + t];
        const float4 xk2 = slev[2 * FIN * SP4 + f * SP4 + t];
        const float4 xk3 = slev[3 * FIN * SP4 + f * SP4 + t];
        const float4 xk4 = slev[4 * FIN * SP4 + f * SP4 + t];

        #pragma unroll
        for (int oo = 0; oo < FOUT / 2; ++oo) {
            const int o = o_base + oo;
            const float w0 = sw[0 * FIN * FOUT + f * FOUT + o];
            const float w1 = sw[1 * FIN * FOUT + f * FOUT + o];
            const float w2 = sw[2 * FIN * FOUT + f * FOUT + o];
            const float w3 = sw[3 * FIN * FOUT + f * FOUT + o];
            const float w4 = sw[4 * FIN * FOUT + f * FOUT + o];
            c[oo].x += xk0.x*w0 + xk1.x*w1 + xk2.x*w2 + xk3.x*w3 + xk4.x*w4;
            c[oo].y += xk0.y*w0 + xk1.y*w1 + xk2.y*w2 + xk3.y*w3 + xk4.y*w4;
            c[oo].z += xk0.z*w0 + xk1.z*w1 + xk2.z*w2 + xk3.z*w3 + xk4.z*w4;
            c[oo].w += xk0.w*w0 + xk1.w*w1 + xk2.w*w2 + xk3.w*w3 + xk4.w*w4;
        }
    }

    #pragma unroll
    for (int oo = 0; oo < FOUT / 2; ++oo)
        out[(size_t)(o_base + oo) * (NV * SP4) + (size_t)v * SP4 + t] = c[oo];
}

#define FINAL_SMEM (KCH * FIN * SP4 * sizeof(float4) + \
                    (KCH * FIN * FOUT + FOUT) * sizeof(float) + \
                    DEG * sizeof(int) + DEG * sizeof(float) + 64)

extern "C" void kernel_launch(void* const* d_in, const int* in_sizes, int n_in,
                              void* d_out, int out_size) {
    const float* inputs = (const float*)d_in[0];
    // d_in[1] = lap_rows (unused: rows are repeat(arange(V), DEG) by construction)
    const int*   cols   = (const int*)d_in[2];
    const float* vals   = (const float*)d_in[3];
    const float* weight = (const float*)d_in[4];
    const float* bias   = (const float*)d_in[5];
    float4*      out    = (float4*)d_out;

    void* sym = nullptr;
    cudaGetSymbolAddress(&sym, g_buf);
    float4* g0 = (float4*)sym;
    float4* g1 = g0 + (size_t)NV * DD4;
    float4* g2 = g1 + (size_t)NV * DD4;

    static int attr_set = 0;
    if (!attr_set) {
        cudaFuncSetAttribute(final_kernel,
                             cudaFuncAttributeMaxDynamicSharedMemorySize,
                             (int)FINAL_SMEM);
        attr_set = 1;
    }

    const float4* in4 = (const float4*)inputs;
    const int IVS4 = SP4;            // input vertex stride (float4)
    const int IFS4 = NV * SP4;       // input feature stride (float4)

    // x1 = L @ x0 (x0 read directly from inputs layout)
    spmv_step_kernel<<<NV, SP4>>>(in4, IVS4, IFS4, nullptr, 0, 0,
                                  g0, cols, vals, 0);
    // x2 = 2 L x1 - x0
    spmv_step_kernel<<<NV, SP4>>>(g0, DD4, SP4, in4, IVS4, IFS4,
                                  g1, cols, vals, 1);
    // x3 = 2 L x2 - x1
    spmv_step_kernel<<<NV, SP4>>>(g1, DD4, SP4, g0, DD4, SP4,
                                  g2, cols, vals, 1);
    // x4 + einsum, smem-staged
    final_kernel<<<NV, 2 * SP4, FINAL_SMEM>>>(in4, g0, g1, g2, cols, vals,
                                              weight, bias, out);
}